// round 5
// baseline (speedup 1.0000x reference)
#include <cuda_runtime.h>
#include <cfloat>
#include <math.h>

#define NMAX   100000
#define HID    128
#define S1     50
#define S2     10
#define WPAD   132
#define TILE   16

// ---------------- scratch (static __device__, no allocations) ----------------
__device__ __align__(16) float4 g_featP[NMAX];                 // padded features
__device__ __align__(16) float  g_h1[(size_t)NMAX * HID];      // enc1 output
__device__ float g_scores[NMAX];
__device__ float g_pm[256];
__device__ float g_ps[256];
__device__ float g_MS[2];

// ---------------- f32x2 helpers ----------------
__device__ __forceinline__ unsigned long long pack2f(float a, float b) {
    unsigned long long r;
    asm("mov.b64 %0, {%1, %2};" : "=l"(r) : "f"(a), "f"(b));
    return r;
}
__device__ __forceinline__ float2 unpack2f(unsigned long long v) {
    float2 r;
    asm("mov.b64 {%0, %1}, %2;" : "=f"(r.x), "=f"(r.y) : "l"(v));
    return r;
}
__device__ __forceinline__ void ffma2(unsigned long long& d, unsigned long long a, unsigned long long b) {
    asm("fma.rn.f32x2 %0, %1, %2, %0;" : "+l"(d) : "l"(a), "l"(b));
}

// matvec for 8 nodes: out[j] = init + sum_k wrow[k] * x[j][k], x node-major stride WPAD
template<int K>
__device__ __forceinline__ void matvec8(const float* __restrict__ wrow,
                                        const float* __restrict__ xbase,
                                        float init, float out[8]) {
    unsigned long long acc[8];
    unsigned long long ini = pack2f(init, 0.f);
#pragma unroll
    for (int j = 0; j < 8; j++) acc[j] = ini;
#pragma unroll 4
    for (int k = 0; k < K; k += 4) {
        ulonglong2 wp = *(const ulonglong2*)(wrow + k);   // (w0,w1),(w2,w3)
#pragma unroll
        for (int j = 0; j < 8; j++) {
            ulonglong2 xp = *(const ulonglong2*)(xbase + j * WPAD + k);
            ffma2(acc[j], xp.x, wp.x);
            ffma2(acc[j], xp.y, wp.y);
        }
    }
#pragma unroll
    for (int j = 0; j < 8; j++) {
        float2 p = unpack2f(acc[j]);
        out[j] = p.x + p.y;
    }
}

// ---------------- kernel 0: pad features [N,3] -> float4 ----------------
__global__ void k_pad(const float* __restrict__ f, int NN) {
    int i = blockIdx.x * blockDim.x + threadIdx.x;
    if (i < NN) {
        g_featP[i] = make_float4(f[3 * i], f[3 * i + 1], f[3 * i + 2], 0.f);
    }
}

// ---------------- kernel 1: enc1 -> h1, one warp per node ----------------
__global__ void k_enc1(const int* __restrict__ n1, const float* __restrict__ W1, int NN) {
    int node = (blockIdx.x << 3) + (threadIdx.x >> 5);
    int lane = threadIdx.x & 31;
    if (node >= NN) return;
    const int* nb = n1 + (size_t)node * S1;
    float a0, a1, a2;
    {
        int i1 = nb[lane];
        float4 f = g_featP[i1];
        a0 = f.x; a1 = f.y; a2 = f.z;
    }
    if (lane < S1 - 32) {
        int i2 = nb[lane + 32];
        float4 f = g_featP[i2];
        a0 += f.x; a1 += f.y; a2 += f.z;
    }
#pragma unroll
    for (int off = 16; off; off >>= 1) {
        a0 += __shfl_xor_sync(0xffffffffu, a0, off);
        a1 += __shfl_xor_sync(0xffffffffu, a1, off);
        a2 += __shfl_xor_sync(0xffffffffu, a2, off);
    }
    float4 fs = g_featP[node];
    const float inv = 1.f / (float)(S1 + 1);
    a0 = (a0 + fs.x) * inv;
    a1 = (a1 + fs.y) * inv;
    a2 = (a2 + fs.z) * inv;
    const float* w = W1 + lane * 12;     // rows 4*lane .. 4*lane+3, 48B aligned
    float4 h;
    h.x = fmaxf(fmaf(a0, w[0], fmaf(a1, w[1],  a2 * w[2])),  0.f);
    h.y = fmaxf(fmaf(a0, w[3], fmaf(a1, w[4],  a2 * w[5])),  0.f);
    h.z = fmaxf(fmaf(a0, w[6], fmaf(a1, w[7],  a2 * w[8])),  0.f);
    h.w = fmaxf(fmaf(a0, w[9], fmaf(a1, w[10], a2 * w[11])), 0.f);
    *(float4*)(g_h1 + (size_t)node * HID + (lane << 2)) = h;
}

// ---------------- kernel 2: enc2 + MLP + scores ----------------
// 256 threads, 16 nodes/tile, all weights in shared, f32x2 FMA.
__global__ void __launch_bounds__(256, 1)
k2(const int* __restrict__ nodes, const int* __restrict__ n2,
   const float* __restrict__ W2g, const float* __restrict__ wag,
   const float* __restrict__ bag, const float* __restrict__ wbg,
   const float* __restrict__ bbg, const float* __restrict__ wcg,
   const float* __restrict__ bcg, const int* __restrict__ psp,
   const int* __restrict__ nep, int Nq, int numTiles) {
    extern __shared__ float sh[];
    float* W2s  = sh;                      // 128*132
    float* was  = W2s  + 128 * WPAD;       // 128*132
    float* waL  = was  + 128 * WPAD;       // 128 (last col of w_a)
    float* wbs  = waL  + 128;              // 64*132
    float* wcs  = wbs  + 64 * WPAD;        // 64
    float* bas  = wcs  + 64;               // 128
    float* bbs  = bas  + 128;              // 64
    float* xs   = bbs  + 64;               // 16*132 node-major
    float* ys   = xs   + TILE * WPAD;      // 16*132 node-major
    float* pbuf = ys   + TILE * WPAD;      // 128*9 (layer-b partials, pad 9)
    float* sbuf = pbuf + 128 * 9;          // 32

    int tid = threadIdx.x;
    for (int i = tid; i < 128 * 128; i += 256) W2s[(i >> 7) * WPAD + (i & 127)] = W2g[i];
    for (int i = tid; i < 128 * 129; i += 256) {
        int r = i / 129, k = i - r * 129;
        if (k < 128) was[r * WPAD + k] = wag[i]; else waL[r] = wag[i];
    }
    for (int i = tid; i < 64 * 128; i += 256) wbs[(i >> 7) * WPAD + (i & 127)] = wbg[i];
    if (tid < 64)  wcs[tid] = wcg[tid];
    if (tid < 128) bas[tid] = bag[tid];
    if (tid < 64)  bbs[tid] = bbg[tid];
    float rem = (float)(psp[0] - nep[0]);
    float bcv = bcg[0];
    __syncthreads();

    int g    = tid >> 7;        // group 0/1 (nodes 0-7 / 8-15)
    int r    = tid & 127;       // output row
    int lane = tid & 31;
    int wid  = tid >> 5;
    int rz   = r & 63;          // layer-b row
    int ko   = (r >> 6) << 6;   // layer-b k offset (0 or 64)

    for (int tile = blockIdx.x; tile < numTiles; tile += gridDim.x) {
        int base = tile * TILE;
        // ---- phase A: gather agg2 (warp handles 2 nodes, coalesced 512B rows)
#pragma unroll
        for (int s2 = 0; s2 < 2; s2++) {
            int n = (wid << 1) + s2;
            int node = base + n;
            float4 acc = make_float4(0.f, 0.f, 0.f, 0.f);
            if (node < Nq) {
                int q = nodes[node];
                acc = *(const float4*)(g_h1 + (size_t)q * HID + (lane << 2));
                const int* nb = n2 + (size_t)q * S2;
#pragma unroll
                for (int jj = 0; jj < S2; jj++) {
                    int qq = nb[jj];
                    float4 u = *(const float4*)(g_h1 + (size_t)qq * HID + (lane << 2));
                    acc.x += u.x; acc.y += u.y; acc.z += u.z; acc.w += u.w;
                }
                const float inv = 1.f / (float)(S2 + 1);
                acc.x *= inv; acc.y *= inv; acc.z *= inv; acc.w *= inv;
            }
            *(float4*)(xs + n * WPAD + (lane << 2)) = acc;
        }
        __syncthreads();

        const float* xg = xs + (g << 3) * WPAD;
        const float* yg = ys + (g << 3) * WPAD;
        float v[8];

        // ---- emb = relu(W2 @ agg2)
        matvec8<128>(W2s + r * WPAD, xg, 0.f, v);
#pragma unroll
        for (int j = 0; j < 8; j++) ys[((g << 3) + j) * WPAD + r] = fmaxf(v[j], 0.f);
        __syncthreads();

        // ---- ya = relu(w_a @ [emb; rem] + b_a)  -> back into xs
        float ini = bas[r] + waL[r] * rem;
        matvec8<128>(was + r * WPAD, yg, ini, v);
#pragma unroll
        for (int j = 0; j < 8; j++) xs[((g << 3) + j) * WPAD + r] = fmaxf(v[j], 0.f);
        __syncthreads();

        // ---- layer b (k-split over thread halves so all SMSPs stay busy)
        matvec8<64>(wbs + rz * WPAD + ko, xg + ko, 0.f, v);
        if (r >= 64) {
#pragma unroll
            for (int j = 0; j < 8; j++) pbuf[((g << 6) + rz) * 9 + j] = v[j];
        }
        __syncthreads();

        if (r < 64) {
            float c[8];
#pragma unroll
            for (int j = 0; j < 8; j++) {
                float z = fmaxf(v[j] + pbuf[((g << 6) + r) * 9 + j] + bbs[r], 0.f);
                c[j] = wcs[r] * z;
            }
#pragma unroll
            for (int off = 16; off; off >>= 1) {
#pragma unroll
                for (int j = 0; j < 8; j++) c[j] += __shfl_xor_sync(0xffffffffu, c[j], off);
            }
            if (lane == 0) {
#pragma unroll
                for (int j = 0; j < 8; j++) sbuf[((g << 1) + (wid & 1)) * 8 + j] = c[j];
            }
        }
        __syncthreads();
        if (tid < 16) {
            int gg = tid >> 3, j = tid & 7;
            int node = base + (gg << 3) + j;
            if (node < Nq) {
                g_scores[node] = sbuf[(gg << 1) * 8 + j] + sbuf[((gg << 1) + 1) * 8 + j] + bcv;
            }
        }
        __syncthreads();
    }
}

// ---------------- softmax (online max+sumexp) ----------------
__device__ __forceinline__ void sm_comb(float& m, float& s, float mo, float so) {
    if (mo > m) { float t = m; m = mo; mo = t; t = s; s = so; so = t; }
    if (so != 0.f) s += so * expf(mo - m);
}

__global__ void k_red1(int N) {
    float m = -FLT_MAX, s = 0.f;
    for (int i = blockIdx.x * blockDim.x + threadIdx.x; i < N; i += gridDim.x * blockDim.x) {
        float x = g_scores[i];
        if (x > m) { s = s * expf(m - x) + 1.f; m = x; }
        else        s += expf(x - m);
    }
#pragma unroll
    for (int off = 16; off; off >>= 1) {
        float mo = __shfl_xor_sync(0xffffffffu, m, off);
        float so = __shfl_xor_sync(0xffffffffu, s, off);
        sm_comb(m, s, mo, so);
    }
    __shared__ float shm[8], shs[8];
    int lane = threadIdx.x & 31, wid = threadIdx.x >> 5;
    if (lane == 0) { shm[wid] = m; shs[wid] = s; }
    __syncthreads();
    if (threadIdx.x < 32) {
        float m2 = (lane < 8) ? shm[lane] : -FLT_MAX;
        float s2 = (lane < 8) ? shs[lane] : 0.f;
#pragma unroll
        for (int off = 4; off; off >>= 1) {
            float mo = __shfl_xor_sync(0xffffffffu, m2, off);
            float so = __shfl_xor_sync(0xffffffffu, s2, off);
            sm_comb(m2, s2, mo, so);
        }
        if (threadIdx.x == 0) { g_pm[blockIdx.x] = m2; g_ps[blockIdx.x] = s2; }
    }
}

__global__ void k_red2(int RB) {
    int t = threadIdx.x;
    float m = (t < RB) ? g_pm[t] : -FLT_MAX;
    float s = (t < RB) ? g_ps[t] : 0.f;
#pragma unroll
    for (int off = 16; off; off >>= 1) {
        float mo = __shfl_xor_sync(0xffffffffu, m, off);
        float so = __shfl_xor_sync(0xffffffffu, s, off);
        sm_comb(m, s, mo, so);
    }
    __shared__ float shm[8], shs[8];
    int lane = t & 31, wid = t >> 5;
    if (lane == 0) { shm[wid] = m; shs[wid] = s; }
    __syncthreads();
    if (t < 32) {
        float m2 = (lane < 8) ? shm[lane] : -FLT_MAX;
        float s2 = (lane < 8) ? shs[lane] : 0.f;
#pragma unroll
        for (int off = 4; off; off >>= 1) {
            float mo = __shfl_xor_sync(0xffffffffu, m2, off);
            float so = __shfl_xor_sync(0xffffffffu, s2, off);
            sm_comb(m2, s2, mo, so);
        }
        if (t == 0) { g_MS[0] = m2; g_MS[1] = 1.f / s2; }
    }
}

__global__ void k_norm(float* __restrict__ out, int N) {
    int i = blockIdx.x * blockDim.x + threadIdx.x;
    if (i < N) out[i] = expf(g_scores[i] - g_MS[0]) * g_MS[1];
}

// ---------------- launch ----------------
static const int SMEM2 = (128 * WPAD + 128 * WPAD + 128 + 64 * WPAD + 64 + 128 + 64
                          + TILE * WPAD + TILE * WPAD + 128 * 9 + 32) * (int)sizeof(float);

extern "C" void kernel_launch(void* const* d_in, const int* in_sizes, int n_in,
                              void* d_out, int out_size) {
    const int*   nodes = (const int*)d_in[0];
    const float* feat  = (const float*)d_in[1];
    const int*   n1    = (const int*)d_in[2];
    const int*   n2    = (const int*)d_in[3];
    const float* W1    = (const float*)d_in[4];
    const float* W2    = (const float*)d_in[5];
    const float* wa    = (const float*)d_in[6];
    const float* ba    = (const float*)d_in[7];
    const float* wb    = (const float*)d_in[8];
    const float* bb    = (const float*)d_in[9];
    const float* wc    = (const float*)d_in[10];
    const float* bc    = (const float*)d_in[11];
    const int*   ps    = (const int*)d_in[12];
    const int*   ne    = (const int*)d_in[13];

    int Nq = in_sizes[0];
    int NN = in_sizes[1] / 3;

    cudaFuncSetAttribute(k2, cudaFuncAttributeMaxDynamicSharedMemorySize, SMEM2);

    k_pad<<<(NN + 255) / 256, 256>>>(feat, NN);
    k_enc1<<<(NN + 7) / 8, 256>>>(n1, W1, NN);

    int numTiles = (Nq + TILE - 1) / TILE;
    k2<<<152, 256, SMEM2>>>(nodes, n2, W2, wa, ba, wb, bb, wc, bc, ps, ne, Nq, numTiles);

    k_red1<<<240, 256>>>(Nq);
    k_red2<<<1, 256>>>(240);
    k_norm<<<(Nq + 255) / 256, 256>>>((float*)d_out, Nq);
}